// round 1
// baseline (speedup 1.0000x reference)
#include <cuda_runtime.h>
#include <cuda_bf16.h>
#include <math.h>

// Problem constants (fixed by the reference)
#define NPSD   256          // L*D = flat node repr dim
#define SINT   32           // intersection set size
#define RELD_  32
#define INPF   32           // node_feat dim
#define DD     64           // dist emb dim
#define GDIM   864          // g_rep dim: 256+256+32+256+32+32
#define MDDIM  320          // md dim: 256 + 64
#define H1DIM  64
#define H2DIM  32

#define LPB    16           // links per block
#define NTHR   256

// shared layout (floats):
//  sg    : LPB*GDIM      = 13824
//  sdist : LPB*64        = 1024
//  sh1   : LPB*64        = 1024
//  sh2   : LPB*32        = 512
//  red   : 4*64*LPB      = 4096
//  ints  : sidx LPB*S=512, shead/stail/srel/sdisti 4*LPB=64
#define SMEM_FLOATS (LPB*GDIM + LPB*64 + LPB*64 + LPB*32 + 4*64*LPB)
#define SMEM_INTS   (LPB*SINT + 4*LPB)
#define SMEM_BYTES  ((SMEM_FLOATS + SMEM_INTS) * 4)

__global__ void __launch_bounds__(NTHR, 2) gcw_fused(
    const float* __restrict__ flat,      // [N, 256]
    const float* __restrict__ feat,      // [N, 32]
    const int*   __restrict__ head_idx,  // [B]
    const int*   __restrict__ rel_idx,   // [B]
    const int*   __restrict__ tail_idx,  // [B]
    const int*   __restrict__ dist_idx,  // [B]
    const int*   __restrict__ inter,     // [B, 32]
    const float* __restrict__ rel_emb,   // [200, 32]
    const float* __restrict__ dist_emb,  // [11, 64]
    const float* __restrict__ headW,     // [320, 32]
    const float* __restrict__ headb,     // [32]
    const float* __restrict__ tailW,     // [320, 32]
    const float* __restrict__ tailb,     // [32]
    const float* __restrict__ W1,        // [864, 64]
    const float* __restrict__ b1,        // [64]
    const float* __restrict__ W2,        // [64, 32]
    const float* __restrict__ b2,        // [32]
    const float* __restrict__ W3,        // [32, 1]
    const float* __restrict__ b3,        // [1]
    float* __restrict__ out, int B)
{
    extern __shared__ float sh[];
    float* sg    = sh;                       // [LPB][GDIM]
    float* sdist = sg    + LPB * GDIM;       // [LPB][64]
    float* sh1   = sdist + LPB * 64;         // [LPB][64]
    float* sh2   = sh1   + LPB * 64;         // [LPB][32]
    float* red   = sh2   + LPB * 32;         // [4*64][LPB]
    int*   sidx  = (int*)(red + 4 * 64 * LPB);  // [LPB][S]
    int*   shead = sidx  + LPB * SINT;
    int*   stail = shead + LPB;
    int*   srel  = stail + LPB;
    int*   sdi   = srel  + LPB;

    const int t  = threadIdx.x;
    const int b0 = blockIdx.x * LPB;

    // ---- load per-link indices ----
    if (t < LPB) {
        int b = min(b0 + t, B - 1);
        shead[t] = head_idx[b];
        stail[t] = tail_idx[b];
        srel[t]  = rel_idx[b];
        sdi[t]   = dist_idx[b];
    }
    for (int i = t; i < LPB * SINT; i += NTHR) {
        int gi = min(b0 * SINT + i, B * SINT - 1);
        sidx[i] = inter[gi];
    }
    __syncthreads();

    // ---- gather head/tail reprs (thread t = column t of 256) ----
    #pragma unroll 4
    for (int l = 0; l < LPB; l++) {
        sg[l * GDIM + t]       = flat[(long)shead[l] * NPSD + t];
        sg[l * GDIM + 256 + t] = flat[(long)stail[l] * NPSD + t];
    }
    // rel_repr, head/tail feats
    #pragma unroll
    for (int rep = 0; rep < 2; rep++) {
        int u = rep * NTHR + t;      // 0..511
        int l = u >> 5, j = u & 31;
        sg[l * GDIM + 512 + j] = rel_emb[(long)srel[l] * RELD_ + j];
        sg[l * GDIM + 800 + j] = feat[(long)shead[l] * INPF + j];
        sg[l * GDIM + 832 + j] = feat[(long)stail[l] * INPF + j];
    }
    // dist_repr
    #pragma unroll
    for (int rep = 0; rep < 4; rep++) {
        int u = rep * NTHR + t;      // 0..1023
        int l = u >> 6, j = u & 63;
        sdist[l * 64 + j] = dist_emb[(long)sdi[l] * DD + j];
    }

    // ---- mid: masked-mean gather (thread t = column t) ----
    #pragma unroll 1
    for (int l = 0; l < LPB; l++) {
        float acc = 0.f;
        int cnt = 0;
        #pragma unroll 8
        for (int s = 0; s < SINT; s++) {
            int c = sidx[l * SINT + s];
            int a = c < 0 ? -c : c;
            float sgn = (float)((c > -1) - (c < -1));   // sign(c+1)
            cnt += (c != -1);
            acc += flat[(long)a * NPSD + t] * sgn;
        }
        cnt = max(cnt, 1);
        sg[l * GDIM + 544 + t] = acc / (float)cnt;
    }
    __syncthreads();

    // ---- head_pred / tail_pred: md[320] @ {head,tail}_W[320,32] ----
    {
        int j  = t & 63;             // 0..31 head, 32..63 tail
        int qg = t >> 6;             // link group: links 4*qg .. 4*qg+3
        int jj = j & 31;
        const float* W  = (j < 32) ? headW : tailW;
        const float* bb = (j < 32) ? headb : tailb;
        float acc[4] = {0.f, 0.f, 0.f, 0.f};

        for (int k = 0; k < 256; k += 4) {
            float w0 = W[(k    ) * INPF + jj];
            float w1 = W[(k + 1) * INPF + jj];
            float w2 = W[(k + 2) * INPF + jj];
            float w3 = W[(k + 3) * INPF + jj];
            #pragma unroll
            for (int i = 0; i < 4; i++) {
                const float4 m = *(const float4*)&sg[(4 * qg + i) * GDIM + 544 + k];
                acc[i] = fmaf(m.x, w0, acc[i]);
                acc[i] = fmaf(m.y, w1, acc[i]);
                acc[i] = fmaf(m.z, w2, acc[i]);
                acc[i] = fmaf(m.w, w3, acc[i]);
            }
        }
        for (int k = 0; k < 64; k += 4) {
            float w0 = W[(256 + k    ) * INPF + jj];
            float w1 = W[(256 + k + 1) * INPF + jj];
            float w2 = W[(256 + k + 2) * INPF + jj];
            float w3 = W[(256 + k + 3) * INPF + jj];
            #pragma unroll
            for (int i = 0; i < 4; i++) {
                const float4 m = *(const float4*)&sdist[(4 * qg + i) * 64 + k];
                acc[i] = fmaf(m.x, w0, acc[i]);
                acc[i] = fmaf(m.y, w1, acc[i]);
                acc[i] = fmaf(m.z, w2, acc[i]);
                acc[i] = fmaf(m.w, w3, acc[i]);
            }
        }
        // outputs: [0,B) out, [B, B+B*32) head_pred, then tail_pred, head_feat, tail_feat
        #pragma unroll
        for (int i = 0; i < 4; i++) {
            int b = b0 + 4 * qg + i;
            if (b < B) {
                float v = acc[i] + bb[jj];
                if (j < 32) out[B + (long)b * 32 + jj] = v;
                else        out[B + (long)B * 32 + (long)b * 32 + jj] = v;
            }
        }
    }

    // ---- emit head/tail init feats ----
    {
        long hf = (long)B + 2L * B * 32;
        long tf = (long)B + 3L * B * 32;
        #pragma unroll
        for (int rep = 0; rep < 2; rep++) {
            int u = rep * NTHR + t;
            int l = u >> 5, j = u & 31;
            int b = b0 + l;
            if (b < B) {
                out[hf + (long)b * 32 + j] = sg[l * GDIM + 800 + j];
                out[tf + (long)b * 32 + j] = sg[l * GDIM + 832 + j];
            }
        }
    }

    // ---- W1: g_rep[864] @ W1[864,64], split-K over 4 thread groups ----
    {
        int j = t & 63;
        int q = t >> 6;              // k-range quarter
        float acc[LPB];
        #pragma unroll
        for (int l = 0; l < LPB; l++) acc[l] = 0.f;

        const int k0 = q * 216;
        for (int k = k0; k < k0 + 216; k += 4) {
            float w0 = W1[(k    ) * 64 + j];
            float w1 = W1[(k + 1) * 64 + j];
            float w2 = W1[(k + 2) * 64 + j];
            float w3 = W1[(k + 3) * 64 + j];
            #pragma unroll
            for (int l = 0; l < LPB; l++) {
                const float4 g = *(const float4*)&sg[l * GDIM + k];
                acc[l] = fmaf(g.x, w0, acc[l]);
                acc[l] = fmaf(g.y, w1, acc[l]);
                acc[l] = fmaf(g.z, w2, acc[l]);
                acc[l] = fmaf(g.w, w3, acc[l]);
            }
        }
        #pragma unroll
        for (int l = 0; l < LPB; l++) red[t * LPB + l] = acc[l];
    }
    __syncthreads();

    // ---- reduce partials + bias + relu -> sh1 ----
    #pragma unroll
    for (int rep = 0; rep < (LPB * 64) / NTHR; rep++) {   // 4 reps
        int p = rep * NTHR + t;      // p = j*LPB + l
        int j = p >> 4, l = p & 15;
        float s = red[(0 * 64 + j) * LPB + l]
                + red[(1 * 64 + j) * LPB + l]
                + red[(2 * 64 + j) * LPB + l]
                + red[(3 * 64 + j) * LPB + l];
        sh1[l * 64 + j] = fmaxf(s + b1[j], 0.f);
    }
    __syncthreads();

    // ---- W2: h1[64] @ W2[64,32] + relu ----
    #pragma unroll
    for (int rep = 0; rep < (LPB * 32) / NTHR; rep++) {   // 2 reps
        int p = rep * NTHR + t;
        int j = p & 31, l = p >> 5;
        float a = 0.f;
        for (int k = 0; k < 64; k += 4) {
            float w0 = W2[(k    ) * 32 + j];
            float w1 = W2[(k + 1) * 32 + j];
            float w2 = W2[(k + 2) * 32 + j];
            float w3 = W2[(k + 3) * 32 + j];
            const float4 h = *(const float4*)&sh1[l * 64 + k];
            a = fmaf(h.x, w0, a);
            a = fmaf(h.y, w1, a);
            a = fmaf(h.z, w2, a);
            a = fmaf(h.w, w3, a);
        }
        sh2[l * 32 + j] = fmaxf(a + b2[j], 0.f);
    }
    __syncthreads();

    // ---- W3: h2[32] @ W3[32,1] -> out[b] ----
    {
        int w = t >> 5, lane = t & 31;
        #pragma unroll
        for (int l = w; l < LPB; l += 8) {
            float v = sh2[l * 32 + lane] * W3[lane];
            #pragma unroll
            for (int off = 16; off > 0; off >>= 1)
                v += __shfl_xor_sync(0xFFFFFFFFu, v, off);
            if (lane == 0 && (b0 + l) < B)
                out[b0 + l] = v + b3[0];
        }
    }
}

extern "C" void kernel_launch(void* const* d_in, const int* in_sizes, int n_in,
                              void* d_out, int out_size)
{
    const float* flat     = (const float*)d_in[0];
    const float* feat     = (const float*)d_in[1];
    const int*   head_idx = (const int*)  d_in[2];
    const int*   rel_idx  = (const int*)  d_in[3];
    const int*   tail_idx = (const int*)  d_in[4];
    const int*   dist_idx = (const int*)  d_in[5];
    const int*   inter    = (const int*)  d_in[6];
    const float* rel_emb  = (const float*)d_in[7];
    const float* dist_emb = (const float*)d_in[8];
    const float* headW    = (const float*)d_in[9];
    const float* headb    = (const float*)d_in[10];
    const float* tailW    = (const float*)d_in[11];
    const float* tailb    = (const float*)d_in[12];
    const float* W1       = (const float*)d_in[13];
    const float* b1       = (const float*)d_in[14];
    const float* W2       = (const float*)d_in[15];
    const float* b2       = (const float*)d_in[16];
    const float* W3       = (const float*)d_in[17];
    const float* b3       = (const float*)d_in[18];

    int B = in_sizes[2];   // head_idx element count

    cudaFuncSetAttribute(gcw_fused, cudaFuncAttributeMaxDynamicSharedMemorySize, SMEM_BYTES);

    int grid = (B + LPB - 1) / LPB;
    gcw_fused<<<grid, NTHR, SMEM_BYTES>>>(
        flat, feat, head_idx, rel_idx, tail_idx, dist_idx, inter,
        rel_emb, dist_emb, headW, headb, tailW, tailb,
        W1, b1, W2, b2, W3, b3,
        (float*)d_out, B);
}

// round 2
// speedup vs baseline: 2.2326x; 2.2326x over previous
#include <cuda_runtime.h>
#include <cuda_bf16.h>
#include <math.h>

// Problem constants (fixed by the reference)
#define NPSD   256          // L*D = flat node repr dim
#define SINT   32           // intersection set size
#define RELD_  32
#define INPF   32           // node_feat dim
#define DD     64           // dist emb dim
#define GDIM   864          // g_rep dim: 256+256+32+256+32+32
#define H1DIM  64
#define H2DIM  32

#define LPB    8            // links per block
#define NTHR   256

// shared layout (floats):
//  sg    : LPB*GDIM      = 6912
//  sdist : LPB*64        = 512
//  sh1   : LPB*64        = 512
//  sh2   : LPB*32        = 256
//  red   : LPB*256       = 2048   (layout red[l*256 + q*64 + j])
//  ints  : sidx LPB*S=256, shead/stail/srel/sdisti 4*LPB=32
#define SMEM_FLOATS (LPB*GDIM + LPB*64 + LPB*64 + LPB*32 + LPB*256)
#define SMEM_INTS   (LPB*SINT + 4*LPB)
#define SMEM_BYTES  ((SMEM_FLOATS + SMEM_INTS) * 4)

__global__ void __launch_bounds__(NTHR, 3) gcw_fused(
    const float* __restrict__ flat,      // [N, 256]
    const float* __restrict__ feat,      // [N, 32]
    const int*   __restrict__ head_idx,  // [B]
    const int*   __restrict__ rel_idx,   // [B]
    const int*   __restrict__ tail_idx,  // [B]
    const int*   __restrict__ dist_idx,  // [B]
    const int*   __restrict__ inter,     // [B, 32]
    const float* __restrict__ rel_emb,   // [200, 32]
    const float* __restrict__ dist_emb,  // [11, 64]
    const float* __restrict__ headW,     // [320, 32]
    const float* __restrict__ headb,     // [32]
    const float* __restrict__ tailW,     // [320, 32]
    const float* __restrict__ tailb,     // [32]
    const float* __restrict__ W1,        // [864, 64]
    const float* __restrict__ b1,        // [64]
    const float* __restrict__ W2,        // [64, 32]
    const float* __restrict__ b2,        // [32]
    const float* __restrict__ W3,        // [32, 1]
    const float* __restrict__ b3,        // [1]
    float* __restrict__ out, int B)
{
    extern __shared__ float sh[];
    float* sg    = sh;                          // [LPB][GDIM]
    float* sdist = sg    + LPB * GDIM;          // [LPB][64]
    float* sh1   = sdist + LPB * 64;            // [LPB][64]
    float* sh2   = sh1   + LPB * 64;            // [LPB][32]
    float* red   = sh2   + LPB * 32;            // [LPB][4*64]  (red[l*256 + t])
    int*   sidx  = (int*)(red + LPB * 256);     // [LPB][S]
    int*   shead = sidx  + LPB * SINT;
    int*   stail = shead + LPB;
    int*   srel  = stail + LPB;
    int*   sdi   = srel  + LPB;

    const int t  = threadIdx.x;
    const int b0 = blockIdx.x * LPB;

    // ---- load per-link indices ----
    if (t < LPB) {
        int b = min(b0 + t, B - 1);
        shead[t] = head_idx[b];
        stail[t] = tail_idx[b];
        srel[t]  = rel_idx[b];
        sdi[t]   = dist_idx[b];
    }
    {
        int gi = min(b0 * SINT + t, B * SINT - 1);   // LPB*SINT == NTHR
        sidx[t] = inter[gi];
    }
    __syncthreads();

    const int g  = t >> 6;          // 0..3
    const int c4 = (t & 63) * 4;    // float4 column base within 256

    // ---- gather head/tail reprs (float4: 64 threads cover 256 cols) ----
    #pragma unroll
    for (int li = 0; li < 2; li++) {
        int l = g + li * 4;
        float4 h = *(const float4*)&flat[(long)shead[l] * NPSD + c4];
        float4 tl = *(const float4*)&flat[(long)stail[l] * NPSD + c4];
        *(float4*)&sg[l * GDIM + c4]       = h;
        *(float4*)&sg[l * GDIM + 256 + c4] = tl;
    }
    // rel_repr, head/tail feats  (LPB*32 == NTHR)
    {
        int l = t >> 5, j = t & 31;
        sg[l * GDIM + 512 + j] = rel_emb[(long)srel[l] * RELD_ + j];
        sg[l * GDIM + 800 + j] = feat[(long)shead[l] * INPF + j];
        sg[l * GDIM + 832 + j] = feat[(long)stail[l] * INPF + j];
    }
    // dist_repr (LPB*64 = 512 -> 2 reps)
    #pragma unroll
    for (int rep = 0; rep < 2; rep++) {
        int u = rep * NTHR + t;
        int l = u >> 6, j = u & 63;
        sdist[l * 64 + j] = dist_emb[(long)sdi[l] * DD + j];
    }

    // ---- mid: masked-mean gather, float4 per thread ----
    #pragma unroll
    for (int li = 0; li < 2; li++) {
        int l = g + li * 4;
        float4 a0 = make_float4(0.f, 0.f, 0.f, 0.f);
        float4 a1 = make_float4(0.f, 0.f, 0.f, 0.f);
        int cnt = 0;
        #pragma unroll 4
        for (int s = 0; s < SINT; s += 2) {
            int i0 = sidx[l * SINT + s];
            int i1 = sidx[l * SINT + s + 1];
            int a0i = i0 < 0 ? -i0 : i0;
            int a1i = i1 < 0 ? -i1 : i1;
            float s0 = (float)((i0 > -1) - (i0 < -1));
            float s1 = (float)((i1 > -1) - (i1 < -1));
            cnt += (i0 != -1) + (i1 != -1);
            const float4 v0 = *(const float4*)&flat[(long)a0i * NPSD + c4];
            const float4 v1 = *(const float4*)&flat[(long)a1i * NPSD + c4];
            a0.x = fmaf(v0.x, s0, a0.x);
            a0.y = fmaf(v0.y, s0, a0.y);
            a0.z = fmaf(v0.z, s0, a0.z);
            a0.w = fmaf(v0.w, s0, a0.w);
            a1.x = fmaf(v1.x, s1, a1.x);
            a1.y = fmaf(v1.y, s1, a1.y);
            a1.z = fmaf(v1.z, s1, a1.z);
            a1.w = fmaf(v1.w, s1, a1.w);
        }
        float inv = 1.f / (float)max(cnt, 1);
        float4 r;
        r.x = (a0.x + a1.x) * inv;
        r.y = (a0.y + a1.y) * inv;
        r.z = (a0.z + a1.z) * inv;
        r.w = (a0.w + a1.w) * inv;
        *(float4*)&sg[l * GDIM + 544 + c4] = r;
    }
    __syncthreads();

    // ---- head_pred / tail_pred: md[320] @ {head,tail}_W[320,32] ----
    {
        int j  = t & 63;             // 0..31 head, 32..63 tail
        int qg = t >> 6;             // link pair: links 2*qg, 2*qg+1
        int jj = j & 31;
        const float* W  = (j < 32) ? headW : tailW;
        const float* bb = (j < 32) ? headb : tailb;
        float acc[2] = {0.f, 0.f};

        for (int k = 0; k < 256; k += 4) {
            float w0 = W[(k    ) * INPF + jj];
            float w1 = W[(k + 1) * INPF + jj];
            float w2 = W[(k + 2) * INPF + jj];
            float w3 = W[(k + 3) * INPF + jj];
            #pragma unroll
            for (int i = 0; i < 2; i++) {
                const float4 m = *(const float4*)&sg[(2 * qg + i) * GDIM + 544 + k];
                acc[i] = fmaf(m.x, w0, acc[i]);
                acc[i] = fmaf(m.y, w1, acc[i]);
                acc[i] = fmaf(m.z, w2, acc[i]);
                acc[i] = fmaf(m.w, w3, acc[i]);
            }
        }
        for (int k = 0; k < 64; k += 4) {
            float w0 = W[(256 + k    ) * INPF + jj];
            float w1 = W[(256 + k + 1) * INPF + jj];
            float w2 = W[(256 + k + 2) * INPF + jj];
            float w3 = W[(256 + k + 3) * INPF + jj];
            #pragma unroll
            for (int i = 0; i < 2; i++) {
                const float4 m = *(const float4*)&sdist[(2 * qg + i) * 64 + k];
                acc[i] = fmaf(m.x, w0, acc[i]);
                acc[i] = fmaf(m.y, w1, acc[i]);
                acc[i] = fmaf(m.z, w2, acc[i]);
                acc[i] = fmaf(m.w, w3, acc[i]);
            }
        }
        #pragma unroll
        for (int i = 0; i < 2; i++) {
            int b = b0 + 2 * qg + i;
            if (b < B) {
                float v = acc[i] + bb[jj];
                if (j < 32) out[B + (long)b * 32 + jj] = v;
                else        out[B + (long)B * 32 + (long)b * 32 + jj] = v;
            }
        }
    }

    // ---- emit head/tail init feats (LPB*32 == NTHR) ----
    {
        long hf = (long)B + 2L * B * 32;
        long tf = (long)B + 3L * B * 32;
        int l = t >> 5, j = t & 31;
        int b = b0 + l;
        if (b < B) {
            out[hf + (long)b * 32 + j] = sg[l * GDIM + 800 + j];
            out[tf + (long)b * 32 + j] = sg[l * GDIM + 832 + j];
        }
    }

    // ---- W1: g_rep[864] @ W1[864,64], split-K over 4 thread groups ----
    {
        int j = t & 63;
        int q = t >> 6;              // k-range quarter
        float acc[LPB];
        #pragma unroll
        for (int l = 0; l < LPB; l++) acc[l] = 0.f;

        const int k0 = q * 216;
        for (int k = k0; k < k0 + 216; k += 4) {
            float w0 = W1[(k    ) * 64 + j];
            float w1 = W1[(k + 1) * 64 + j];
            float w2 = W1[(k + 2) * 64 + j];
            float w3 = W1[(k + 3) * 64 + j];
            #pragma unroll
            for (int l = 0; l < LPB; l++) {
                const float4 gg = *(const float4*)&sg[l * GDIM + k];
                acc[l] = fmaf(gg.x, w0, acc[l]);
                acc[l] = fmaf(gg.y, w1, acc[l]);
                acc[l] = fmaf(gg.z, w2, acc[l]);
                acc[l] = fmaf(gg.w, w3, acc[l]);
            }
        }
        #pragma unroll
        for (int l = 0; l < LPB; l++) red[l * 256 + t] = acc[l];
    }
    __syncthreads();

    // ---- reduce partials + bias + relu -> sh1 (LPB*64 = 512 -> 2 reps) ----
    #pragma unroll
    for (int rep = 0; rep < 2; rep++) {
        int p = rep * NTHR + t;
        int j = p & 63, l = p >> 6;
        float s = red[l * 256 +   0 + j]
                + red[l * 256 +  64 + j]
                + red[l * 256 + 128 + j]
                + red[l * 256 + 192 + j];
        sh1[l * 64 + j] = fmaxf(s + b1[j], 0.f);
    }
    __syncthreads();

    // ---- W2: h1[64] @ W2[64,32] + relu (LPB*32 == NTHR) ----
    {
        int j = t & 31, l = t >> 5;
        float a = 0.f;
        for (int k = 0; k < 64; k += 4) {
            float w0 = W2[(k    ) * 32 + j];
            float w1 = W2[(k + 1) * 32 + j];
            float w2 = W2[(k + 2) * 32 + j];
            float w3 = W2[(k + 3) * 32 + j];
            const float4 h = *(const float4*)&sh1[l * 64 + k];
            a = fmaf(h.x, w0, a);
            a = fmaf(h.y, w1, a);
            a = fmaf(h.z, w2, a);
            a = fmaf(h.w, w3, a);
        }
        sh2[l * 32 + j] = fmaxf(a + b2[j], 0.f);
    }
    __syncthreads();

    // ---- W3: h2[32] @ W3[32,1] -> out[b] (8 warps, 1 link each) ----
    {
        int w = t >> 5, lane = t & 31;
        float v = sh2[w * 32 + lane] * W3[lane];
        #pragma unroll
        for (int off = 16; off > 0; off >>= 1)
            v += __shfl_xor_sync(0xFFFFFFFFu, v, off);
        if (lane == 0 && (b0 + w) < B)
            out[b0 + w] = v + b3[0];
    }
}

extern "C" void kernel_launch(void* const* d_in, const int* in_sizes, int n_in,
                              void* d_out, int out_size)
{
    const float* flat     = (const float*)d_in[0];
    const float* feat     = (const float*)d_in[1];
    const int*   head_idx = (const int*)  d_in[2];
    const int*   rel_idx  = (const int*)  d_in[3];
    const int*   tail_idx = (const int*)  d_in[4];
    const int*   dist_idx = (const int*)  d_in[5];
    const int*   inter    = (const int*)  d_in[6];
    const float* rel_emb  = (const float*)d_in[7];
    const float* dist_emb = (const float*)d_in[8];
    const float* headW    = (const float*)d_in[9];
    const float* headb    = (const float*)d_in[10];
    const float* tailW    = (const float*)d_in[11];
    const float* tailb    = (const float*)d_in[12];
    const float* W1       = (const float*)d_in[13];
    const float* b1       = (const float*)d_in[14];
    const float* W2       = (const float*)d_in[15];
    const float* b2       = (const float*)d_in[16];
    const float* W3       = (const float*)d_in[17];
    const float* b3       = (const float*)d_in[18];

    int B = in_sizes[2];   // head_idx element count

    cudaFuncSetAttribute(gcw_fused, cudaFuncAttributeMaxDynamicSharedMemorySize, SMEM_BYTES);

    int grid = (B + LPB - 1) / LPB;
    gcw_fused<<<grid, NTHR, SMEM_BYTES>>>(
        flat, feat, head_idx, rel_idx, tail_idx, dist_idx, inter,
        rel_emb, dist_emb, headW, headb, tailW, tailb,
        W1, b1, W2, b2, W3, b3,
        (float*)d_out, B);
}

// round 3
// speedup vs baseline: 2.7933x; 1.2511x over previous
#include <cuda_runtime.h>
#include <cuda_bf16.h>
#include <math.h>

// Problem constants (fixed by the reference)
#define NPSD   256          // L*D = flat node repr dim
#define SINT   32           // intersection set size
#define RELD_  32
#define INPF   32           // node_feat dim
#define DD     64           // dist emb dim
#define GDIM   864          // g_rep dim: 256+256+32+256+32+32

#define LPB    8            // links per block
#define NTHR   256

// shared layout (floats):
//  sg    : LPB*GDIM = 6912
//  sdist : LPB*64   = 512
//  sh1   : LPB*64   = 512
//  sh2   : LPB*32   = 256
//  red   : 8*8*64   = 4096   (red[q*512 + l*64 + j]) - reused pred then W1
//  ints  : sidx LPB*S=256, shead/stail/srel/sdi 4*LPB=32
#define SMEM_FLOATS (LPB*GDIM + LPB*64 + LPB*64 + LPB*32 + 8*LPB*64)
#define SMEM_INTS   (LPB*SINT + 4*LPB)
#define SMEM_BYTES  ((SMEM_FLOATS + SMEM_INTS) * 4)

__global__ void __launch_bounds__(NTHR, 3) gcw_fused(
    const float* __restrict__ flat,      // [N, 256]
    const float* __restrict__ feat,      // [N, 32]
    const int*   __restrict__ head_idx,  // [B]
    const int*   __restrict__ rel_idx,   // [B]
    const int*   __restrict__ tail_idx,  // [B]
    const int*   __restrict__ dist_idx,  // [B]
    const int*   __restrict__ inter,     // [B, 32]
    const float* __restrict__ rel_emb,   // [200, 32]
    const float* __restrict__ dist_emb,  // [11, 64]
    const float* __restrict__ headW,     // [320, 32]
    const float* __restrict__ headb,     // [32]
    const float* __restrict__ tailW,     // [320, 32]
    const float* __restrict__ tailb,     // [32]
    const float* __restrict__ W1,        // [864, 64]
    const float* __restrict__ b1,        // [64]
    const float* __restrict__ W2,        // [64, 32]
    const float* __restrict__ b2,        // [32]
    const float* __restrict__ W3,        // [32, 1]
    const float* __restrict__ b3,        // [1]
    float* __restrict__ out, int B)
{
    extern __shared__ float sh[];
    float* sg    = sh;                          // [LPB][GDIM]
    float* sdist = sg    + LPB * GDIM;          // [LPB][64]
    float* sh1   = sdist + LPB * 64;            // [LPB][64]
    float* sh2   = sh1   + LPB * 64;            // [LPB][32]
    float* red   = sh2   + LPB * 32;            // [8][LPB][64]
    int*   sidx  = (int*)(red + 8 * LPB * 64);  // [LPB][S]
    int*   shead = sidx  + LPB * SINT;
    int*   stail = shead + LPB;
    int*   srel  = stail + LPB;
    int*   sdi   = srel  + LPB;

    const int t  = threadIdx.x;
    const int b0 = blockIdx.x * LPB;

    // ---- load per-link indices ----
    if (t < LPB) {
        int b = min(b0 + t, B - 1);
        shead[t] = head_idx[b];
        stail[t] = tail_idx[b];
        srel[t]  = rel_idx[b];
        sdi[t]   = dist_idx[b];
    }
    {
        int gi = min(b0 * SINT + t, B * SINT - 1);   // LPB*SINT == NTHR
        sidx[t] = inter[gi];
    }
    __syncthreads();

    const int g  = t >> 6;          // 0..3
    const int c4 = (t & 63) * 4;    // float4 column base within 256

    // ---- gather head/tail reprs (float4: 64 threads cover 256 cols) ----
    #pragma unroll
    for (int li = 0; li < 2; li++) {
        int l = g + li * 4;
        float4 h  = *(const float4*)&flat[(long)shead[l] * NPSD + c4];
        float4 tl = *(const float4*)&flat[(long)stail[l] * NPSD + c4];
        *(float4*)&sg[l * GDIM + c4]       = h;
        *(float4*)&sg[l * GDIM + 256 + c4] = tl;
    }
    // rel_repr, head/tail feats  (LPB*32 == NTHR)
    {
        int l = t >> 5, j = t & 31;
        sg[l * GDIM + 512 + j] = rel_emb[(long)srel[l] * RELD_ + j];
        sg[l * GDIM + 800 + j] = feat[(long)shead[l] * INPF + j];
        sg[l * GDIM + 832 + j] = feat[(long)stail[l] * INPF + j];
    }
    // dist_repr (LPB*64 = 512 -> 2 reps)
    #pragma unroll
    for (int rep = 0; rep < 2; rep++) {
        int u = rep * NTHR + t;
        int l = u >> 6, j = u & 63;
        sdist[l * 64 + j] = dist_emb[(long)sdi[l] * DD + j];
    }

    // ---- mid: masked-mean gather, float4 per thread ----
    #pragma unroll
    for (int li = 0; li < 2; li++) {
        int l = g + li * 4;
        float4 a0 = make_float4(0.f, 0.f, 0.f, 0.f);
        float4 a1 = make_float4(0.f, 0.f, 0.f, 0.f);
        int cnt = 0;
        #pragma unroll 4
        for (int s = 0; s < SINT; s += 2) {
            int i0 = sidx[l * SINT + s];
            int i1 = sidx[l * SINT + s + 1];
            int a0i = i0 < 0 ? -i0 : i0;
            int a1i = i1 < 0 ? -i1 : i1;
            float s0 = (float)((i0 > -1) - (i0 < -1));
            float s1 = (float)((i1 > -1) - (i1 < -1));
            cnt += (i0 != -1) + (i1 != -1);
            const float4 v0 = *(const float4*)&flat[(long)a0i * NPSD + c4];
            const float4 v1 = *(const float4*)&flat[(long)a1i * NPSD + c4];
            a0.x = fmaf(v0.x, s0, a0.x);
            a0.y = fmaf(v0.y, s0, a0.y);
            a0.z = fmaf(v0.z, s0, a0.z);
            a0.w = fmaf(v0.w, s0, a0.w);
            a1.x = fmaf(v1.x, s1, a1.x);
            a1.y = fmaf(v1.y, s1, a1.y);
            a1.z = fmaf(v1.z, s1, a1.z);
            a1.w = fmaf(v1.w, s1, a1.w);
        }
        float inv = 1.f / (float)max(cnt, 1);
        float4 r;
        r.x = (a0.x + a1.x) * inv;
        r.y = (a0.y + a1.y) * inv;
        r.z = (a0.z + a1.z) * inv;
        r.w = (a0.w + a1.w) * inv;
        *(float4*)&sg[l * GDIM + 544 + c4] = r;
    }

    // ---- emit head/tail init feats (LPB*32 == NTHR) ----
    {
        long hf = (long)B + 2L * B * 32;
        long tf = (long)B + 3L * B * 32;
        int l = t >> 5, j = t & 31;
        int b = b0 + l;
        if (b < B) {
            out[hf + (long)b * 32 + j] = feat[(long)shead[l] * INPF + j];
            out[tf + (long)b * 32 + j] = feat[(long)stail[l] * INPF + j];
        }
    }
    __syncthreads();

    // ---- head/tail pred: md[320] @ W[320,32], jtile=2, 8-way split-K ----
    {
        const int jj2 = (t & 15) * 2;        // 0,2,...,30
        const int sel = (t >> 4) & 1;        // 0=head, 1=tail
        const int q   = t >> 5;              // 0..7
        const float* W = sel ? tailW : headW;
        float acc[LPB][2];
        #pragma unroll
        for (int l = 0; l < LPB; l++) { acc[l][0] = 0.f; acc[l][1] = 0.f; }

        const int k0 = q * 40;
        #pragma unroll 2
        for (int k = k0; k < k0 + 40; k += 4) {
            float2 w0 = *(const float2*)&W[(k    ) * INPF + jj2];
            float2 w1 = *(const float2*)&W[(k + 1) * INPF + jj2];
            float2 w2 = *(const float2*)&W[(k + 2) * INPF + jj2];
            float2 w3 = *(const float2*)&W[(k + 3) * INPF + jj2];
            #pragma unroll
            for (int l = 0; l < LPB; l++) {
                float4 m;
                if (k < 256) m = *(const float4*)&sg[l * GDIM + 544 + k];
                else         m = *(const float4*)&sdist[l * 64 + (k - 256)];
                acc[l][0] = fmaf(m.x, w0.x, acc[l][0]);
                acc[l][1] = fmaf(m.x, w0.y, acc[l][1]);
                acc[l][0] = fmaf(m.y, w1.x, acc[l][0]);
                acc[l][1] = fmaf(m.y, w1.y, acc[l][1]);
                acc[l][0] = fmaf(m.z, w2.x, acc[l][0]);
                acc[l][1] = fmaf(m.z, w2.y, acc[l][1]);
                acc[l][0] = fmaf(m.w, w3.x, acc[l][0]);
                acc[l][1] = fmaf(m.w, w3.y, acc[l][1]);
            }
        }
        #pragma unroll
        for (int l = 0; l < LPB; l++)
            *(float2*)&red[q * 512 + l * 64 + sel * 32 + jj2] =
                make_float2(acc[l][0], acc[l][1]);
    }
    __syncthreads();

    // ---- reduce pred partials + bias -> out ----
    #pragma unroll
    for (int rep = 0; rep < 2; rep++) {
        int p = rep * NTHR + t;
        int l = p >> 6, j = p & 63, jj = j & 31;
        float s = 0.f;
        #pragma unroll
        for (int q = 0; q < 8; q++) s += red[q * 512 + l * 64 + j];
        int b = b0 + l;
        if (b < B) {
            if (j < 32) out[B + (long)b * 32 + jj] = s + headb[jj];
            else        out[B + (long)B * 32 + (long)b * 32 + jj] = s + tailb[jj];
        }
    }
    __syncthreads();   // red reused below

    // ---- W1: g_rep[864] @ W1[864,64], jtile=2, 8-way split-K ----
    {
        const int j2 = (t & 31) * 2;         // 0,2,...,62
        const int q  = t >> 5;               // 0..7
        float acc[LPB][2];
        #pragma unroll
        for (int l = 0; l < LPB; l++) { acc[l][0] = 0.f; acc[l][1] = 0.f; }

        const int k0 = q * 108;
        #pragma unroll 3
        for (int k = k0; k < k0 + 108; k += 4) {
            float2 w0 = *(const float2*)&W1[(k    ) * 64 + j2];
            float2 w1 = *(const float2*)&W1[(k + 1) * 64 + j2];
            float2 w2 = *(const float2*)&W1[(k + 2) * 64 + j2];
            float2 w3 = *(const float2*)&W1[(k + 3) * 64 + j2];
            #pragma unroll
            for (int l = 0; l < LPB; l++) {
                const float4 gg = *(const float4*)&sg[l * GDIM + k];
                acc[l][0] = fmaf(gg.x, w0.x, acc[l][0]);
                acc[l][1] = fmaf(gg.x, w0.y, acc[l][1]);
                acc[l][0] = fmaf(gg.y, w1.x, acc[l][0]);
                acc[l][1] = fmaf(gg.y, w1.y, acc[l][1]);
                acc[l][0] = fmaf(gg.z, w2.x, acc[l][0]);
                acc[l][1] = fmaf(gg.z, w2.y, acc[l][1]);
                acc[l][0] = fmaf(gg.w, w3.x, acc[l][0]);
                acc[l][1] = fmaf(gg.w, w3.y, acc[l][1]);
            }
        }
        #pragma unroll
        for (int l = 0; l < LPB; l++)
            *(float2*)&red[q * 512 + l * 64 + j2] = make_float2(acc[l][0], acc[l][1]);
    }
    __syncthreads();

    // ---- reduce W1 partials + bias + relu -> sh1 ----
    #pragma unroll
    for (int rep = 0; rep < 2; rep++) {
        int p = rep * NTHR + t;
        int l = p >> 6, j = p & 63;
        float s = 0.f;
        #pragma unroll
        for (int q = 0; q < 8; q++) s += red[q * 512 + l * 64 + j];
        sh1[l * 64 + j] = fmaxf(s + b1[j], 0.f);
    }
    __syncthreads();

    // ---- W2: h1[64] @ W2[64,32] + relu (LPB*32 == NTHR) ----
    {
        int j = t & 31, l = t >> 5;
        float a = 0.f;
        #pragma unroll 4
        for (int k = 0; k < 64; k += 4) {
            float w0 = W2[(k    ) * 32 + j];
            float w1 = W2[(k + 1) * 32 + j];
            float w2 = W2[(k + 2) * 32 + j];
            float w3 = W2[(k + 3) * 32 + j];
            const float4 h = *(const float4*)&sh1[l * 64 + k];
            a = fmaf(h.x, w0, a);
            a = fmaf(h.y, w1, a);
            a = fmaf(h.z, w2, a);
            a = fmaf(h.w, w3, a);
        }
        sh2[l * 32 + j] = fmaxf(a + b2[j], 0.f);
    }
    __syncthreads();

    // ---- W3: h2[32] @ W3[32,1] -> out[b] (8 warps, 1 link each) ----
    {
        int w = t >> 5, lane = t & 31;
        float v = sh2[w * 32 + lane] * W3[lane];
        #pragma unroll
        for (int off = 16; off > 0; off >>= 1)
            v += __shfl_xor_sync(0xFFFFFFFFu, v, off);
        if (lane == 0 && (b0 + w) < B)
            out[b0 + w] = v + b3[0];
    }
}

extern "C" void kernel_launch(void* const* d_in, const int* in_sizes, int n_in,
                              void* d_out, int out_size)
{
    const float* flat     = (const float*)d_in[0];
    const float* feat     = (const float*)d_in[1];
    const int*   head_idx = (const int*)  d_in[2];
    const int*   rel_idx  = (const int*)  d_in[3];
    const int*   tail_idx = (const int*)  d_in[4];
    const int*   dist_idx = (const int*)  d_in[5];
    const int*   inter    = (const int*)  d_in[6];
    const float* rel_emb  = (const float*)d_in[7];
    const float* dist_emb = (const float*)d_in[8];
    const float* headW    = (const float*)d_in[9];
    const float* headb    = (const float*)d_in[10];
    const float* tailW    = (const float*)d_in[11];
    const float* tailb    = (const float*)d_in[12];
    const float* W1       = (const float*)d_in[13];
    const float* b1       = (const float*)d_in[14];
    const float* W2       = (const float*)d_in[15];
    const float* b2       = (const float*)d_in[16];
    const float* W3       = (const float*)d_in[17];
    const float* b3       = (const float*)d_in[18];

    int B = in_sizes[2];   // head_idx element count

    cudaFuncSetAttribute(gcw_fused, cudaFuncAttributeMaxDynamicSharedMemorySize, SMEM_BYTES);

    int grid = (B + LPB - 1) / LPB;
    gcw_fused<<<grid, NTHR, SMEM_BYTES>>>(
        flat, feat, head_idx, rel_idx, tail_idx, dist_idx, inter,
        rel_emb, dist_emb, headW, headb, tailW, tailb,
        W1, b1, W2, b2, W3, b3,
        (float*)d_out, B);
}